// round 13
// baseline (speedup 1.0000x reference)
#include <cuda_runtime.h>
#include <cuda_fp16.h>
#include <math.h>
#include <cstdint>

#define BATCH 4
#define SEQ   2048
#define DM    1024
#define NH    64
#define NSP   4      // key splits per q-tile

// ---------------- scratch (no cudaMalloc allowed) ----------------
__device__ __half g_q[BATCH * SEQ * NH];    // fp16, pre-scaled by 0.125
__device__ __half g_k[BATCH * SEQ * NH];    // fp16
__device__ __half g_v[BATCH * SEQ * NH];    // fp16 row-major [s][h]
__device__ __half g_vt[BATCH * NH * SEQ];   // fp16 transposed [h][s]
__device__ __half g_wt[192 * DM];           // W^T (q|k|v rows), fp16
__device__ float  g_po[BATCH * NSP * SEQ * NH];  // partial O (unnormalized)
__device__ float  g_pm[BATCH * NSP * SEQ];       // partial row max
__device__ float  g_pl[BATCH * NSP * SEQ];       // partial row sum

// mma.sync m16n8k16 fp16 (sm_80+ PTX; tensor pipe)
__device__ __forceinline__ void mma_f16(float d[4], const uint32_t a[4],
                                        uint32_t b0, uint32_t b1) {
    asm volatile(
        "mma.sync.aligned.m16n8k16.row.col.f32.f16.f16.f32 "
        "{%0,%1,%2,%3}, {%4,%5,%6,%7}, {%8,%9}, {%0,%1,%2,%3};\n"
        : "+f"(d[0]), "+f"(d[1]), "+f"(d[2]), "+f"(d[3])
        : "r"(a[0]), "r"(a[1]), "r"(a[2]), "r"(a[3]), "r"(b0), "r"(b1));
}

__device__ __forceinline__ uint2 c4h(float4 v) {
    __half2 a = __floats2half2_rn(v.x, v.y);
    __half2 b = __floats2half2_rn(v.z, v.w);
    uint2 r;
    r.x = *(uint32_t*)&a;
    r.y = *(uint32_t*)&b;
    return r;
}

// =================================================================
// Kernel 0: transpose W (q|k|v) -> g_wt[192][1024] fp16.
// 16x64 tiles, grid (64, 3): 192 blocks (latency-bound kernel).
// =================================================================
__global__ __launch_bounds__(256) void wt_kernel(
    const float* __restrict__ Wq,
    const float* __restrict__ Wk,
    const float* __restrict__ Wv)
{
    __shared__ float t[16][65];
    const int tid = threadIdx.x;
    const int k0  = blockIdx.x * 16;
    const int y   = blockIdx.y;
    const float* W = (y == 0) ? Wq : (y == 1) ? Wk : Wv;

    #pragma unroll
    for (int i = 0; i < 4; i++) {
        const int idx = tid + i * 256;
        const int kk = idx >> 6, nn = idx & 63;
        t[kk][nn] = W[(k0 + kk) * NH + nn];
    }
    __syncthreads();
    #pragma unroll
    for (int i = 0; i < 4; i++) {
        const int idx = tid + i * 256;
        const int nn = idx >> 4, kk = idx & 15;
        g_wt[(y * 64 + nn) * DM + k0 + kk] = __float2half(t[kk][nn]);
    }
}

// =================================================================
// Kernel 1: QKV projection, fp16 m16n8k16.
// Block: M=32 x N=192, grid 256 (~1.7 blocks/SM). 8 warps (2m x 4n),
// warp tile m16 x n48. Double-buffered smem, 2-deep LDG prefetch,
// 1 barrier/chunk. Outputs fp16 (q pre-scaled by 0.125), V row-major.
// =================================================================
#define QST 40

__global__ __launch_bounds__(256) void qkv_mma_kernel(
    const float* __restrict__ x,
    const float* __restrict__ bq,
    const float* __restrict__ bk,
    const float* __restrict__ bv)
{
    __shared__ __half As[2][32][QST];
    __shared__ __half Bs[2][192][QST];
    __shared__ float bias_sm[192];

    const int tid  = threadIdx.x;
    const int wid  = tid >> 5;
    const int lane = tid & 31;
    const int m0   = blockIdx.x * 32;
    const int wm   = wid >> 2;            // 0..1 -> rows wm*16
    const int wn   = wid & 3;             // 0..3 -> cols wn*48
    const int gid  = lane >> 2;
    const int tig  = lane & 3;

    if (tid < 64)        bias_sm[tid] = bq[tid];
    else if (tid < 128)  bias_sm[tid] = bk[tid - 64];
    else if (tid < 192)  bias_sm[tid] = bv[tid - 128];

    float d[6][4];
    #pragma unroll
    for (int j = 0; j < 6; j++)
        #pragma unroll
        for (int c = 0; c < 4; c++) d[j][c] = 0.f;

    // x load: row = tid>>3 (32 rows), seg = (tid&7)*4 -> 1 float4/thread
    // W load: idx = tid + 256i (i<3): row = idx>>2, seg = (idx&3)*8
    float4 rx[2];
    uint4  rw[2][3];

    auto ldg_chunk = [&](int c, int slot) {
        const int kc = c * 32;
        rx[slot] = *(const float4*)&x[(size_t)(m0 + (tid >> 3)) * DM + kc + (tid & 7) * 4];
        #pragma unroll
        for (int i = 0; i < 3; i++) {
            const int idx = tid + 256 * i;
            rw[slot][i] = *(const uint4*)&g_wt[(size_t)(idx >> 2) * DM + kc + (idx & 3) * 8];
        }
    };
    auto commit_chunk = [&](int slot, int buf) {
        *(uint2*)&As[buf][tid >> 3][(tid & 7) * 4] = c4h(rx[slot]);
        #pragma unroll
        for (int i = 0; i < 3; i++) {
            const int idx = tid + 256 * i;
            *(uint4*)&Bs[buf][idx >> 2][(idx & 3) * 8] = rw[slot][i];
        }
    };

    const int NC = DM / 32;  // 32 chunks
    ldg_chunk(0, 0);
    ldg_chunk(1, 1);
    commit_chunk(0, 0);
    ldg_chunk(2, 0);
    __syncthreads();

    for (int it = 0; it < NC; it++) {
        const int buf = it & 1;
        #pragma unroll
        for (int ks = 0; ks < 2; ks++) {
            const int k0 = ks * 16;
            uint32_t a[4];
            const int r = wm * 16 + gid;
            a[0] = *(const uint32_t*)&As[buf][r][k0 + 2 * tig];
            a[1] = *(const uint32_t*)&As[buf][r + 8][k0 + 2 * tig];
            a[2] = *(const uint32_t*)&As[buf][r][k0 + 2 * tig + 8];
            a[3] = *(const uint32_t*)&As[buf][r + 8][k0 + 2 * tig + 8];
            #pragma unroll
            for (int nt = 0; nt < 6; nt++) {
                const int n = wn * 48 + nt * 8 + gid;
                const uint32_t b0 = *(const uint32_t*)&Bs[buf][n][k0 + 2 * tig];
                const uint32_t b1 = *(const uint32_t*)&Bs[buf][n][k0 + 2 * tig + 8];
                mma_f16(d[nt], a, b0, b1);
            }
        }
        if (it + 1 < NC) commit_chunk((it + 1) & 1, (it + 1) & 1);
        if (it + 3 < NC) ldg_chunk(it + 3, (it + 1) & 1);
        __syncthreads();
    }

    // epilogue: bias + (scale q) + fp16 store (row-major)
    const int row = m0 + wm * 16 + gid;
    #pragma unroll
    for (int nt = 0; nt < 6; nt++) {
        const int col0 = wn * 48 + nt * 8;
        __half* dst = (col0 < 64) ? g_q : (col0 < 128) ? g_k : g_v;
        const float scale = (col0 < 64) ? 0.125f : 1.0f;
        const int h0 = (col0 & 63) + 2 * tig;
        const float b0 = bias_sm[col0 + 2 * tig];
        const float b1 = bias_sm[col0 + 2 * tig + 1];
        __half2 w0 = __floats2half2_rn((d[nt][0] + b0) * scale,
                                       (d[nt][1] + b1) * scale);
        __half2 w1 = __floats2half2_rn((d[nt][2] + b0) * scale,
                                       (d[nt][3] + b1) * scale);
        *(uint32_t*)&dst[(size_t)row * NH + h0]       = *(uint32_t*)&w0;
        *(uint32_t*)&dst[(size_t)(row + 8) * NH + h0] = *(uint32_t*)&w1;
    }
}

// =================================================================
// Kernel 1b: transpose V -> g_vt [b][h][s] fp16 (restored from R10).
// =================================================================
__global__ __launch_bounds__(256) void vt_kernel()
{
    __shared__ __half t[64][72];
    const int tid = threadIdx.x;
    const int s0  = blockIdx.x * 64;
    const int b   = blockIdx.y;
    const __half* src = g_v + (size_t)b * SEQ * NH;
    __half* dst = g_vt + (size_t)b * NH * SEQ;

    #pragma unroll
    for (int i = 0; i < 2; i++) {
        const int idx = tid + 256 * i;
        const int row = idx >> 3, seg = (idx & 7) * 8;
        *(uint4*)&t[row][seg] = *(const uint4*)&src[(size_t)(s0 + row) * NH + seg];
    }
    __syncthreads();
    #pragma unroll
    for (int i = 0; i < 2; i++) {
        const int idx = tid + 256 * i;
        const int h = idx >> 3, seg = (idx & 7) * 8;
        uint32_t w[4];
        #pragma unroll
        for (int j = 0; j < 4; j++) {
            __half2 hh = __halves2half2(t[seg + 2 * j][h], t[seg + 2 * j + 1][h]);
            w[j] = *(uint32_t*)&hh;
        }
        uint4 o = make_uint4(w[0], w[1], w[2], w[3]);
        *(uint4*)&dst[(size_t)h * SEQ + s0 + seg] = o;
    }
}

// =================================================================
// Kernel 2: split-K causal flash attention (unchanged — known good).
// =================================================================
#define AST 72

__global__ __launch_bounds__(64) void attn_split_kernel()
{
    __shared__ __half ks[2][64][AST];
    __shared__ __half vs[2][64][AST];

    const int tid = threadIdx.x;
    const int qt  = 63 - blockIdx.x;      // heavy blocks first
    const int sp  = blockIdx.y;
    const int b   = blockIdx.z;
    const int q0  = qt * 32;
    const int nk  = (qt >> 1) + 1;
    const int ts  = (nk + NSP - 1) / NSP;
    const int tb  = sp * ts;
    const int te  = (tb + ts < nk) ? (tb + ts) : nk;

    float* PO = g_po + ((size_t)(b * NSP + sp) * SEQ + q0) * NH;
    float* PM = g_pm + (size_t)(b * NSP + sp) * SEQ + q0;
    float* PL = g_pl + (size_t)(b * NSP + sp) * SEQ + q0;

    if (tb >= nk) {
        #pragma unroll
        for (int i = 0; i < 4; i++) {
            const int idx = tid + 64 * i;
            const int row = idx >> 3, cg = (idx & 7) * 8;
            float4 z = make_float4(0.f, 0.f, 0.f, 0.f);
            *(float4*)&PO[(size_t)row * NH + cg]     = z;
            *(float4*)&PO[(size_t)row * NH + cg + 4] = z;
        }
        if (tid < 32) { PM[tid] = -1e30f; PL[tid] = 0.f; }
        return;
    }

    const __half* Q  = g_q  + (size_t)b * SEQ * NH;
    const __half* K  = g_k  + (size_t)b * SEQ * NH;
    const __half* VT = g_vt + (size_t)b * NH * SEQ;

    const int wid  = tid >> 5;
    const int lane = tid & 31;
    const int gid  = lane >> 2;
    const int tig  = lane & 3;
    const int r0   = wid * 16 + gid;
    const int r1   = r0 + 8;

    uint32_t qa[4][4];
    #pragma unroll
    for (int kc = 0; kc < 4; kc++) {
        const __half* p0 = &Q[(size_t)(q0 + r0) * NH + kc * 16 + 2 * tig];
        const __half* p1 = &Q[(size_t)(q0 + r1) * NH + kc * 16 + 2 * tig];
        qa[kc][0] = *(const uint32_t*)p0;
        qa[kc][1] = *(const uint32_t*)p1;
        qa[kc][2] = *(const uint32_t*)(p0 + 8);
        qa[kc][3] = *(const uint32_t*)(p1 + 8);
    }

    {
        const int kb = tb * 64;
        #pragma unroll
        for (int i = 0; i < 8; i++) {
            const int idx = tid + 64 * i;
            const int row = idx >> 3, seg = (idx & 7) * 8;
            *(uint4*)&ks[tb & 1][row][seg] =
                *(const uint4*)&K[(size_t)(kb + row) * NH + seg];
            *(uint4*)&vs[tb & 1][row][seg] =
                *(const uint4*)&VT[(size_t)row * SEQ + kb + seg];
        }
    }
    __syncthreads();

    float m0 = -1e30f, m1 = -1e30f, l0 = 0.f, l1 = 0.f;
    float d_o[8][4];
    #pragma unroll
    for (int nt = 0; nt < 8; nt++)
        #pragma unroll
        for (int c = 0; c < 4; c++) d_o[nt][c] = 0.f;

    for (int t = tb; t < te; t++) {
        if (t + 1 < te) {
            const int kb = (t + 1) * 64;
            const int bn = (t + 1) & 1;
            #pragma unroll
            for (int i = 0; i < 8; i++) {
                const int idx = tid + 64 * i;
                const int row = idx >> 3, seg = (idx & 7) * 8;
                *(uint4*)&ks[bn][row][seg] =
                    *(const uint4*)&K[(size_t)(kb + row) * NH + seg];
                *(uint4*)&vs[bn][row][seg] =
                    *(const uint4*)&VT[(size_t)row * SEQ + kb + seg];
            }
        }

        float sd[8][4];
        #pragma unroll
        for (int nt = 0; nt < 8; nt++)
            #pragma unroll
            for (int c = 0; c < 4; c++) sd[nt][c] = 0.f;
        {
            const __half (*kt)[AST] = ks[t & 1];
            #pragma unroll
            for (int kc = 0; kc < 4; kc++) {
                #pragma unroll
                for (int nt = 0; nt < 8; nt++) {
                    const __half* kp = &kt[8 * nt + gid][kc * 16 + 2 * tig];
                    mma_f16(sd[nt], qa[kc],
                            *(const uint32_t*)kp, *(const uint32_t*)(kp + 8));
                }
            }
        }

        if (t == nk - 1) {
            #pragma unroll
            for (int nt = 0; nt < 8; nt++) {
                const int kg = t * 64 + 8 * nt + 2 * tig;
                if (kg     > q0 + r0) sd[nt][0] = -1e30f;
                if (kg + 1 > q0 + r0) sd[nt][1] = -1e30f;
                if (kg     > q0 + r1) sd[nt][2] = -1e30f;
                if (kg + 1 > q0 + r1) sd[nt][3] = -1e30f;
            }
        }

        float t0 = -1e30f, t1 = -1e30f;
        #pragma unroll
        for (int nt = 0; nt < 8; nt++) {
            t0 = fmaxf(t0, fmaxf(sd[nt][0], sd[nt][1]));
            t1 = fmaxf(t1, fmaxf(sd[nt][2], sd[nt][3]));
        }
        t0 = fmaxf(t0, __shfl_xor_sync(0xffffffffu, t0, 1));
        t0 = fmaxf(t0, __shfl_xor_sync(0xffffffffu, t0, 2));
        t1 = fmaxf(t1, __shfl_xor_sync(0xffffffffu, t1, 1));
        t1 = fmaxf(t1, __shfl_xor_sync(0xffffffffu, t1, 2));
        const float mn0 = fmaxf(m0, t0);
        const float mn1 = fmaxf(m1, t1);
        const float f0 = __expf(m0 - mn0);
        const float f1 = __expf(m1 - mn1);
        m0 = mn0; m1 = mn1;
        #pragma unroll
        for (int nt = 0; nt < 8; nt++) {
            d_o[nt][0] *= f0; d_o[nt][1] *= f0;
            d_o[nt][2] *= f1; d_o[nt][3] *= f1;
        }

        uint32_t pa[4][4];
        float s0 = 0.f, s1 = 0.f;
        #pragma unroll
        for (int nt = 0; nt < 8; nt++) {
            __half2 h0 = __floats2half2_rn(__expf(sd[nt][0] - mn0),
                                           __expf(sd[nt][1] - mn0));
            __half2 h1 = __floats2half2_rn(__expf(sd[nt][2] - mn1),
                                           __expf(sd[nt][3] - mn1));
            float2 g0 = __half22float2(h0);
            float2 g1 = __half22float2(h1);
            s0 += g0.x + g0.y;
            s1 += g1.x + g1.y;
            const int kc = nt >> 1;
            if ((nt & 1) == 0) {
                pa[kc][0] = *(uint32_t*)&h0;
                pa[kc][1] = *(uint32_t*)&h1;
            } else {
                pa[kc][2] = *(uint32_t*)&h0;
                pa[kc][3] = *(uint32_t*)&h1;
            }
        }
        s0 += __shfl_xor_sync(0xffffffffu, s0, 1);
        s0 += __shfl_xor_sync(0xffffffffu, s0, 2);
        s1 += __shfl_xor_sync(0xffffffffu, s1, 1);
        s1 += __shfl_xor_sync(0xffffffffu, s1, 2);
        l0 = l0 * f0 + s0;
        l1 = l1 * f1 + s1;

        {
            const __half (*vt)[AST] = vs[t & 1];
            #pragma unroll
            for (int kc = 0; kc < 4; kc++) {
                #pragma unroll
                for (int nt = 0; nt < 8; nt++) {
                    const __half* vp = &vt[8 * nt + gid][kc * 16 + 2 * tig];
                    mma_f16(d_o[nt], pa[kc],
                            *(const uint32_t*)vp, *(const uint32_t*)(vp + 8));
                }
            }
        }
        __syncthreads();
    }

    if (tig == 0) {
        PM[r0] = m0; PL[r0] = l0;
        PM[r1] = m1; PL[r1] = l1;
    }
    #pragma unroll
    for (int nt = 0; nt < 8; nt++) {
        const int cc = 8 * nt + 2 * tig;
        *(float2*)&PO[(size_t)r0 * NH + cc] = make_float2(d_o[nt][0], d_o[nt][1]);
        *(float2*)&PO[(size_t)r1 * NH + cc] = make_float2(d_o[nt][2], d_o[nt][3]);
    }
}

// =================================================================
// Kernel 3: combine partials -> out.
// Grid (SEQ/16, BATCH), 256 threads: row = tid>>4, 4 cols/thread.
// All loads hoisted for ILP (kernel is latency-bound).
// =================================================================
__global__ __launch_bounds__(256) void comb_kernel(float* __restrict__ out)
{
    const int tid = threadIdx.x;
    const int s   = blockIdx.x * 16 + (tid >> 4);
    const int b   = blockIdx.y;
    const int cg  = (tid & 15) * 4;

    float m[NSP], l[NSP];
    float4 o[NSP];
    #pragma unroll
    for (int i = 0; i < NSP; i++) {
        m[i] = g_pm[(size_t)(b * NSP + i) * SEQ + s];
        l[i] = g_pl[(size_t)(b * NSP + i) * SEQ + s];
        o[i] = *(const float4*)&g_po[((size_t)(b * NSP + i) * SEQ + s) * NH + cg];
    }
    float M = m[0];
    #pragma unroll
    for (int i = 1; i < NSP; i++) M = fmaxf(M, m[i]);
    float w[NSP], L = 0.f;
    #pragma unroll
    for (int i = 0; i < NSP; i++) {
        w[i] = __expf(m[i] - M);
        L += w[i] * l[i];
    }
    const float inv = 1.f / L;

    float4 acc = make_float4(0.f, 0.f, 0.f, 0.f);
    #pragma unroll
    for (int i = 0; i < NSP; i++) {
        acc.x += w[i] * o[i].x;
        acc.y += w[i] * o[i].y;
        acc.z += w[i] * o[i].z;
        acc.w += w[i] * o[i].w;
    }
    *(float4*)&out[(size_t)(b * SEQ + s) * NH + cg] =
        make_float4(acc.x * inv, acc.y * inv, acc.z * inv, acc.w * inv);
}

// =================================================================
// launch
// =================================================================
extern "C" void kernel_launch(void* const* d_in, const int* in_sizes, int n_in,
                              void* d_out, int out_size)
{
    (void)in_sizes; (void)n_in; (void)out_size;
    const float* x  = (const float*)d_in[0];
    const float* Wq = (const float*)d_in[1];
    const float* bq = (const float*)d_in[2];
    const float* Wk = (const float*)d_in[3];
    const float* bk = (const float*)d_in[4];
    const float* Wv = (const float*)d_in[5];
    const float* bv = (const float*)d_in[6];
    float* out = (float*)d_out;

    wt_kernel<<<dim3(64, 3), 256>>>(Wq, Wk, Wv);
    qkv_mma_kernel<<<(BATCH * SEQ) / 32, 256>>>(x, bq, bk, bv);
    vt_kernel<<<dim3(SEQ / 64, BATCH), 256>>>();
    attn_split_kernel<<<dim3(64, NSP, BATCH), 64>>>();
    comb_kernel<<<dim3(SEQ / 16, BATCH), 256>>>(out);
}

// round 15
// speedup vs baseline: 1.6918x; 1.6918x over previous
#include <cuda_runtime.h>
#include <cuda_fp16.h>
#include <math.h>
#include <cstdint>

#define BATCH 4
#define SEQ   2048
#define DM    1024
#define NH    64
#define NSP   4      // key splits per q-tile

// ---------------- scratch (no cudaMalloc allowed) ----------------
__device__ __half g_q[BATCH * SEQ * NH];    // fp16, pre-scaled by 0.125
__device__ __half g_k[BATCH * SEQ * NH];    // fp16
__device__ __half g_v[BATCH * SEQ * NH];    // fp16 row-major [s][h]
__device__ __half g_vt[BATCH * NH * SEQ];   // fp16 transposed [h][s]
__device__ __half g_wt[192 * DM];           // W^T (q|k|v rows), fp16
__device__ float  g_po[BATCH * NSP * SEQ * NH];  // partial O (unnormalized)
__device__ float  g_pm[BATCH * NSP * SEQ];       // partial row max
__device__ float  g_pl[BATCH * NSP * SEQ];       // partial row sum

// mma.sync m16n8k16 fp16 (sm_80+ PTX; tensor pipe)
__device__ __forceinline__ void mma_f16(float d[4], const uint32_t a[4],
                                        uint32_t b0, uint32_t b1) {
    asm volatile(
        "mma.sync.aligned.m16n8k16.row.col.f32.f16.f16.f32 "
        "{%0,%1,%2,%3}, {%4,%5,%6,%7}, {%8,%9}, {%0,%1,%2,%3};\n"
        : "+f"(d[0]), "+f"(d[1]), "+f"(d[2]), "+f"(d[3])
        : "r"(a[0]), "r"(a[1]), "r"(a[2]), "r"(a[3]), "r"(b0), "r"(b1));
}

__device__ __forceinline__ void ldmatrix_x4(uint32_t r[4], uint32_t addr) {
    asm volatile(
        "ldmatrix.sync.aligned.m8n8.x4.shared.b16 {%0,%1,%2,%3}, [%4];\n"
        : "=r"(r[0]), "=r"(r[1]), "=r"(r[2]), "=r"(r[3]) : "r"(addr));
}

__device__ __forceinline__ void cp_async16(uint32_t saddr, const void* gptr) {
    asm volatile("cp.async.cg.shared.global [%0], [%1], 16;\n"
                 :: "r"(saddr), "l"(gptr));
}
__device__ __forceinline__ void cp_commit() {
    asm volatile("cp.async.commit_group;\n");
}
__device__ __forceinline__ void cp_wait0() {
    asm volatile("cp.async.wait_group 0;\n");
}

__device__ __forceinline__ uint32_t smem_u32(const void* p) {
    uint32_t a;
    asm("{ .reg .u64 t; cvta.to.shared.u64 t, %1; cvt.u32.u64 %0, t; }"
        : "=r"(a) : "l"(p));
    return a;
}

__device__ __forceinline__ uint2 c4h(float4 v) {
    __half2 a = __floats2half2_rn(v.x, v.y);
    __half2 b = __floats2half2_rn(v.z, v.w);
    uint2 r;
    r.x = *(uint32_t*)&a;
    r.y = *(uint32_t*)&b;
    return r;
}

// =================================================================
// Kernel 0: transpose W (q|k|v) -> g_wt[192][1024] fp16.
// =================================================================
__global__ __launch_bounds__(256) void wt_kernel(
    const float* __restrict__ Wq,
    const float* __restrict__ Wk,
    const float* __restrict__ Wv)
{
    __shared__ float t[16][65];
    const int tid = threadIdx.x;
    const int k0  = blockIdx.x * 16;
    const int y   = blockIdx.y;
    const float* W = (y == 0) ? Wq : (y == 1) ? Wk : Wv;

    #pragma unroll
    for (int i = 0; i < 4; i++) {
        const int idx = tid + i * 256;
        const int kk = idx >> 6, nn = idx & 63;
        t[kk][nn] = W[(k0 + kk) * NH + nn];
    }
    __syncthreads();
    #pragma unroll
    for (int i = 0; i < 4; i++) {
        const int idx = tid + i * 256;
        const int nn = idx >> 4, kk = idx & 15;
        g_wt[(y * 64 + nn) * DM + k0 + kk] = __float2half(t[kk][nn]);
    }
}

// =================================================================
// Kernel 1: QKV projection, fp16 m16n8k16.
// M=64 x N=192 per block, grid 128, 8 warps (2m x 4n), warp tile
// m32 x n48. K-chunk = 64 (16 chunks). ldmatrix fragment loads,
// cp.async W pipeline, register-staged x (f32->f16 convert), one
// barrier per chunk. Dynamic smem 74.5 KB, stride 72 halfs.
// =================================================================
#define KC    64
#define QST   72
#define QA_OFF 0
#define QB_OFF (2 * 64 * QST * 2)                 // 18432
#define QBIAS_OFF (QB_OFF + 2 * 192 * QST * 2)    // 73728
#define QSMEM (QBIAS_OFF + 192 * 4)               // 74496

__global__ __launch_bounds__(256) void qkv_mma_kernel(
    const float* __restrict__ x,
    const float* __restrict__ bq,
    const float* __restrict__ bk,
    const float* __restrict__ bv)
{
    extern __shared__ char smem[];
    __half* As = (__half*)(smem + QA_OFF);        // [2][64][72]
    __half* Bs = (__half*)(smem + QB_OFF);        // [2][192][72]
    float* bias_sm = (float*)(smem + QBIAS_OFF);  // [192]
    const uint32_t sA = smem_u32(As);
    const uint32_t sB = smem_u32(Bs);

    const int tid  = threadIdx.x;
    const int wid  = tid >> 5;
    const int lane = tid & 31;
    const int m0   = blockIdx.x * 64;
    const int wm   = wid >> 2;            // 0..1 -> rows wm*32
    const int wn   = wid & 3;             // 0..3 -> cols wn*48
    const int gid  = lane >> 2;
    const int tig  = lane & 3;

    if (tid < 64)        bias_sm[tid] = bq[tid];
    else if (tid < 128)  bias_sm[tid] = bk[tid - 64];
    else if (tid < 192)  bias_sm[tid] = bv[tid - 128];

    float d[2][6][4];
    #pragma unroll
    for (int i = 0; i < 2; i++)
        #pragma unroll
        for (int j = 0; j < 6; j++)
            #pragma unroll
            for (int c = 0; c < 4; c++) d[i][j][c] = 0.f;

    // x: 64 rows x 64 f32 per chunk = 1024 float4; 4/thread.
    const int xr  = tid >> 4;             // rows covered: xr, then +16*... no:
    // idx = tid + 256*i -> row = idx>>4 (16 float4/row), col4 = (idx&15)*4
    // W: 192 rows x 64 halfs = 128B/row = 8 x 16B; 1536 segs, 6/thread.
    float4 rx[4];

    auto ldg_x = [&](int c) {
        const int kc = c * KC;
        #pragma unroll
        for (int i = 0; i < 4; i++) {
            const int idx = tid + 256 * i;
            rx[i] = *(const float4*)&x[(size_t)(m0 + (idx >> 4)) * DM + kc + (idx & 15) * 4];
        }
    };
    auto commit_x = [&](int buf) {
        #pragma unroll
        for (int i = 0; i < 4; i++) {
            const int idx = tid + 256 * i;
            *(uint2*)&As[(buf * 64 + (idx >> 4)) * QST + (idx & 15) * 4] = c4h(rx[i]);
        }
    };
    auto casync_w = [&](int c, int buf) {
        const int kc = c * KC;
        #pragma unroll
        for (int i = 0; i < 6; i++) {
            const int idx = tid + 256 * i;
            const int row = idx >> 3, seg = idx & 7;
            cp_async16(sB + ((buf * 192 + row) * QST + seg * 8) * 2,
                       &g_wt[(size_t)row * DM + kc + seg * 8]);
        }
        cp_commit();
    };

    const int NC = DM / KC;  // 16 chunks

    // prologue
    casync_w(0, 0);
    ldg_x(0);
    casync_w(1, 1);
    commit_x(0);
    ldg_x(1);
    asm volatile("cp.async.wait_group 1;\n");   // W(0) arrived
    __syncthreads();
    // state: Bs[0]+As[0] ready; x(1) in regs; W(1) in flight -> Bs[1]

    for (int it = 0; it < NC; it++) {
        const int buf  = it & 1;
        const int nbuf = buf ^ 1;

        // ---- compute chunk it ----
        #pragma unroll
        for (int ks = 0; ks < 4; ks++) {
            const int k0 = ks * 16;
            uint32_t a[2][4];
            #pragma unroll
            for (int mt = 0; mt < 2; mt++) {
                const int m = wm * 32 + mt * 16 + (lane & 15);
                const int c = k0 + (lane >> 4) * 8;
                ldmatrix_x4(a[mt], sA + ((buf * 64 + m) * QST + c) * 2);
            }
            uint32_t bfr[3][4];
            #pragma unroll
            for (int p = 0; p < 3; p++) {
                const int n = wn * 48 + 16 * p + ((lane >> 4) << 3) + (lane & 7);
                const int c = k0 + ((lane >> 3) & 1) * 8;
                ldmatrix_x4(bfr[p], sB + ((buf * 192 + n) * QST + c) * 2);
            }
            #pragma unroll
            for (int nt = 0; nt < 6; nt++) {
                const int p = nt >> 1;
                const uint32_t b0 = bfr[p][(nt & 1) * 2];
                const uint32_t b1 = bfr[p][(nt & 1) * 2 + 1];
                mma_f16(d[0][nt], a[0][0] == 0xFFFFFFFFu ? a[0] : a[0], b0, b1);
                mma_f16(d[1][nt], a[1], b0, b1);
            }
        }

        // ---- stage next data ----
        if (it + 1 < NC) commit_x(nbuf);          // x(it+1) regs -> As[nbuf]
        if (it + 2 < NC) ldg_x(it + 2);           // x(it+2) -> regs
        if (it + 1 < NC) cp_wait0();              // W(it+1) arrived in Bs[nbuf]
        __syncthreads();                          // all reads of buf done
        if (it + 2 < NC) casync_w(it + 2, buf);   // W(it+2) -> Bs[buf]
    }

    // epilogue: bias + (scale q) + fp16 store (row-major)
    #pragma unroll
    for (int mt = 0; mt < 2; mt++) {
        const int row = m0 + wm * 32 + mt * 16 + gid;
        #pragma unroll
        for (int nt = 0; nt < 6; nt++) {
            const int col0 = wn * 48 + nt * 8;
            __half* dst = (col0 < 64) ? g_q : (col0 < 128) ? g_k : g_v;
            const float scale = (col0 < 64) ? 0.125f : 1.0f;
            const int h0 = (col0 & 63) + 2 * tig;
            const float b0 = bias_sm[col0 + 2 * tig];
            const float b1 = bias_sm[col0 + 2 * tig + 1];
            __half2 w0 = __floats2half2_rn((d[mt][nt][0] + b0) * scale,
                                           (d[mt][nt][1] + b1) * scale);
            __half2 w1 = __floats2half2_rn((d[mt][nt][2] + b0) * scale,
                                           (d[mt][nt][3] + b1) * scale);
            *(uint32_t*)&dst[(size_t)row * NH + h0]       = *(uint32_t*)&w0;
            *(uint32_t*)&dst[(size_t)(row + 8) * NH + h0] = *(uint32_t*)&w1;
        }
    }
}

// =================================================================
// Kernel 1b: transpose V -> g_vt [b][h][s] fp16.
// =================================================================
__global__ __launch_bounds__(256) void vt_kernel()
{
    __shared__ __half t[64][72];
    const int tid = threadIdx.x;
    const int s0  = blockIdx.x * 64;
    const int b   = blockIdx.y;
    const __half* src = g_v + (size_t)b * SEQ * NH;
    __half* dst = g_vt + (size_t)b * NH * SEQ;

    #pragma unroll
    for (int i = 0; i < 2; i++) {
        const int idx = tid + 256 * i;
        const int row = idx >> 3, seg = (idx & 7) * 8;
        *(uint4*)&t[row][seg] = *(const uint4*)&src[(size_t)(s0 + row) * NH + seg];
    }
    __syncthreads();
    #pragma unroll
    for (int i = 0; i < 2; i++) {
        const int idx = tid + 256 * i;
        const int h = idx >> 3, seg = (idx & 7) * 8;
        uint32_t w[4];
        #pragma unroll
        for (int j = 0; j < 4; j++) {
            __half2 hh = __halves2half2(t[seg + 2 * j][h], t[seg + 2 * j + 1][h]);
            w[j] = *(uint32_t*)&hh;
        }
        uint4 o = make_uint4(w[0], w[1], w[2], w[3]);
        *(uint4*)&dst[(size_t)h * SEQ + s0 + seg] = o;
    }
}

// =================================================================
// Kernel 2: split-K causal flash attention (unchanged — known good).
// =================================================================
#define AST 72

__global__ __launch_bounds__(64) void attn_split_kernel()
{
    __shared__ __half ks[2][64][AST];
    __shared__ __half vs[2][64][AST];

    const int tid = threadIdx.x;
    const int qt  = 63 - blockIdx.x;      // heavy blocks first
    const int sp  = blockIdx.y;
    const int b   = blockIdx.z;
    const int q0  = qt * 32;
    const int nk  = (qt >> 1) + 1;
    const int ts  = (nk + NSP - 1) / NSP;
    const int tb  = sp * ts;
    const int te  = (tb + ts < nk) ? (tb + ts) : nk;

    float* PO = g_po + ((size_t)(b * NSP + sp) * SEQ + q0) * NH;
    float* PM = g_pm + (size_t)(b * NSP + sp) * SEQ + q0;
    float* PL = g_pl + (size_t)(b * NSP + sp) * SEQ + q0;

    if (tb >= nk) {
        #pragma unroll
        for (int i = 0; i < 4; i++) {
            const int idx = tid + 64 * i;
            const int row = idx >> 3, cg = (idx & 7) * 8;
            float4 z = make_float4(0.f, 0.f, 0.f, 0.f);
            *(float4*)&PO[(size_t)row * NH + cg]     = z;
            *(float4*)&PO[(size_t)row * NH + cg + 4] = z;
        }
        if (tid < 32) { PM[tid] = -1e30f; PL[tid] = 0.f; }
        return;
    }

    const __half* Q  = g_q  + (size_t)b * SEQ * NH;
    const __half* K  = g_k  + (size_t)b * SEQ * NH;
    const __half* VT = g_vt + (size_t)b * NH * SEQ;

    const int wid  = tid >> 5;
    const int lane = tid & 31;
    const int gid  = lane >> 2;
    const int tig  = lane & 3;
    const int r0   = wid * 16 + gid;
    const int r1   = r0 + 8;

    uint32_t qa[4][4];
    #pragma unroll
    for (int kc = 0; kc < 4; kc++) {
        const __half* p0 = &Q[(size_t)(q0 + r0) * NH + kc * 16 + 2 * tig];
        const __half* p1 = &Q[(size_t)(q0 + r1) * NH + kc * 16 + 2 * tig];
        qa[kc][0] = *(const uint32_t*)p0;
        qa[kc][1] = *(const uint32_t*)p1;
        qa[kc][2] = *(const uint32_t*)(p0 + 8);
        qa[kc][3] = *(const uint32_t*)(p1 + 8);
    }

    {
        const int kb = tb * 64;
        #pragma unroll
        for (int i = 0; i < 8; i++) {
            const int idx = tid + 64 * i;
            const int row = idx >> 3, seg = (idx & 7) * 8;
            *(uint4*)&ks[tb & 1][row][seg] =
                *(const uint4*)&K[(size_t)(kb + row) * NH + seg];
            *(uint4*)&vs[tb & 1][row][seg] =
                *(const uint4*)&VT[(size_t)row * SEQ + kb + seg];
        }
    }
    __syncthreads();

    float m0 = -1e30f, m1 = -1e30f, l0 = 0.f, l1 = 0.f;
    float d_o[8][4];
    #pragma unroll
    for (int nt = 0; nt < 8; nt++)
        #pragma unroll
        for (int c = 0; c < 4; c++) d_o[nt][c] = 0.f;

    for (int t = tb; t < te; t++) {
        if (t + 1 < te) {
            const int kb = (t + 1) * 64;
            const int bn = (t + 1) & 1;
            #pragma unroll
            for (int i = 0; i < 8; i++) {
                const int idx = tid + 64 * i;
                const int row = idx >> 3, seg = (idx & 7) * 8;
                *(uint4*)&ks[bn][row][seg] =
                    *(const uint4*)&K[(size_t)(kb + row) * NH + seg];
                *(uint4*)&vs[bn][row][seg] =
                    *(const uint4*)&VT[(size_t)row * SEQ + kb + seg];
            }
        }

        float sd[8][4];
        #pragma unroll
        for (int nt = 0; nt < 8; nt++)
            #pragma unroll
            for (int c = 0; c < 4; c++) sd[nt][c] = 0.f;
        {
            const __half (*kt)[AST] = ks[t & 1];
            #pragma unroll
            for (int kc = 0; kc < 4; kc++) {
                #pragma unroll
                for (int nt = 0; nt < 8; nt++) {
                    const __half* kp = &kt[8 * nt + gid][kc * 16 + 2 * tig];
                    mma_f16(sd[nt], qa[kc],
                            *(const uint32_t*)kp, *(const uint32_t*)(kp + 8));
                }
            }
        }

        if (t == nk - 1) {
            #pragma unroll
            for (int nt = 0; nt < 8; nt++) {
                const int kg = t * 64 + 8 * nt + 2 * tig;
                if (kg     > q0 + r0) sd[nt][0] = -1e30f;
                if (kg + 1 > q0 + r0) sd[nt][1] = -1e30f;
                if (kg     > q0 + r1) sd[nt][2] = -1e30f;
                if (kg + 1 > q0 + r1) sd[nt][3] = -1e30f;
            }
        }

        float t0 = -1e30f, t1 = -1e30f;
        #pragma unroll
        for (int nt = 0; nt < 8; nt++) {
            t0 = fmaxf(t0, fmaxf(sd[nt][0], sd[nt][1]));
            t1 = fmaxf(t1, fmaxf(sd[nt][2], sd[nt][3]));
        }
        t0 = fmaxf(t0, __shfl_xor_sync(0xffffffffu, t0, 1));
        t0 = fmaxf(t0, __shfl_xor_sync(0xffffffffu, t0, 2));
        t1 = fmaxf(t1, __shfl_xor_sync(0xffffffffu, t1, 1));
        t1 = fmaxf(t1, __shfl_xor_sync(0xffffffffu, t1, 2));
        const float mn0 = fmaxf(m0, t0);
        const float mn1 = fmaxf(m1, t1);
        const float f0 = __expf(m0 - mn0);
        const float f1 = __expf(m1 - mn1);
        m0 = mn0; m1 = mn1;
        #pragma unroll
        for (int nt = 0; nt < 8; nt++) {
            d_o[nt][0] *= f0; d_o[nt][1] *= f0;
            d_o[nt][2] *= f1; d_o[nt][3] *= f1;
        }

        uint32_t pa[4][4];
        float s0 = 0.f, s1 = 0.f;
        #pragma unroll
        for (int nt = 0; nt < 8; nt++) {
            __half2 h0 = __floats2half2_rn(__expf(sd[nt][0] - mn0),
                                           __expf(sd[nt][1] - mn0));
            __half2 h1 = __floats2half2_rn(__expf(sd[nt][2] - mn1),
                                           __expf(sd[nt][3] - mn1));
            float2 g0 = __half22float2(h0);
            float2 g1 = __half22float2(h1);
            s0 += g0.x + g0.y;
            s1 += g1.x + g1.y;
            const int kc = nt >> 1;
            if ((nt & 1) == 0) {
                pa[kc][0] = *(uint32_t*)&h0;
                pa[kc][1] = *(uint32_t*)&h1;
            } else {
                pa[kc][2] = *(uint32_t*)&h0;
                pa[kc][3] = *(uint32_t*)&h1;
            }
        }
        s0 += __shfl_xor_sync(0xffffffffu, s0, 1);
        s0 += __shfl_xor_sync(0xffffffffu, s0, 2);
        s1 += __shfl_xor_sync(0xffffffffu, s1, 1);
        s1 += __shfl_xor_sync(0xffffffffu, s1, 2);
        l0 = l0 * f0 + s0;
        l1 = l1 * f1 + s1;

        {
            const __half (*vt)[AST] = vs[t & 1];
            #pragma unroll
            for (int kc = 0; kc < 4; kc++) {
                #pragma unroll
                for (int nt = 0; nt < 8; nt++) {
                    const __half* vp = &vt[8 * nt + gid][kc * 16 + 2 * tig];
                    mma_f16(d_o[nt], pa[kc],
                            *(const uint32_t*)vp, *(const uint32_t*)(vp + 8));
                }
            }
        }
        __syncthreads();
    }

    if (tig == 0) {
        PM[r0] = m0; PL[r0] = l0;
        PM[r1] = m1; PL[r1] = l1;
    }
    #pragma unroll
    for (int nt = 0; nt < 8; nt++) {
        const int cc = 8 * nt + 2 * tig;
        *(float2*)&PO[(size_t)r0 * NH + cc] = make_float2(d_o[nt][0], d_o[nt][1]);
        *(float2*)&PO[(size_t)r1 * NH + cc] = make_float2(d_o[nt][2], d_o[nt][3]);
    }
}

// =================================================================
// Kernel 3: combine partials -> out.
// =================================================================
__global__ __launch_bounds__(256) void comb_kernel(float* __restrict__ out)
{
    const int tid = threadIdx.x;
    const int s   = blockIdx.x * 16 + (tid >> 4);
    const int b   = blockIdx.y;
    const int cg  = (tid & 15) * 4;

    float m[NSP], l[NSP];
    float4 o[NSP];
    #pragma unroll
    for (int i = 0; i < NSP; i++) {
        m[i] = g_pm[(size_t)(b * NSP + i) * SEQ + s];
        l[i] = g_pl[(size_t)(b * NSP + i) * SEQ + s];
        o[i] = *(const float4*)&g_po[((size_t)(b * NSP + i) * SEQ + s) * NH + cg];
    }
    float M = m[0];
    #pragma unroll
    for (int i = 1; i < NSP; i++) M = fmaxf(M, m[i]);
    float w[NSP], L = 0.f;
    #pragma unroll
    for (int i = 0; i < NSP; i++) {
        w[i] = __expf(m[i] - M);
        L += w[i] * l[i];
    }
    const float inv = 1.f / L;

    float4 acc = make_float4(0.f, 0.f, 0.f, 0.f);
    #pragma unroll
    for (int i = 0; i < NSP; i++) {
        acc.x += w[i] * o[i].x;
        acc.y += w[i] * o[i].y;
        acc.z += w[i] * o[i].z;
        acc.w += w[i] * o[i].w;
    }
    *(float4*)&out[(size_t)(b * SEQ + s) * NH + cg] =
        make_float4(acc.x * inv, acc.y * inv, acc.z * inv, acc.w * inv);
}

// =================================================================
// launch
// =================================================================
extern "C" void kernel_launch(void* const* d_in, const int* in_sizes, int n_in,
                              void* d_out, int out_size)
{
    (void)in_sizes; (void)n_in; (void)out_size;
    const float* x  = (const float*)d_in[0];
    const float* Wq = (const float*)d_in[1];
    const float* bq = (const float*)d_in[2];
    const float* Wk = (const float*)d_in[3];
    const float* bk = (const float*)d_in[4];
    const float* Wv = (const float*)d_in[5];
    const float* bv = (const float*)d_in[6];
    float* out = (float*)d_out;

    cudaFuncSetAttribute(qkv_mma_kernel,
                         cudaFuncAttributeMaxDynamicSharedMemorySize, QSMEM);

    wt_kernel<<<dim3(64, 3), 256>>>(Wq, Wk, Wv);
    qkv_mma_kernel<<<(BATCH * SEQ) / 64, 256, QSMEM>>>(x, bq, bk, bv);
    vt_kernel<<<dim3(SEQ / 64, BATCH), 256>>>();
    attn_split_kernel<<<dim3(64, NSP, BATCH), 64>>>();
    comb_kernel<<<dim3(SEQ / 16, BATCH), 256>>>(out);
}

// round 17
// speedup vs baseline: 1.8485x; 1.0926x over previous
#include <cuda_runtime.h>
#include <cuda_fp16.h>
#include <math.h>
#include <cstdint>

#define BATCH 4
#define SEQ   2048
#define DM    1024
#define NH    64
#define NSP   4      // key splits per q-tile

// ---------------- scratch (no cudaMalloc allowed) ----------------
__device__ __half g_q[BATCH * SEQ * NH];    // fp16, pre-scaled by 0.125
__device__ __half g_k[BATCH * SEQ * NH];    // fp16
__device__ __half g_v[BATCH * SEQ * NH];    // fp16 row-major [s][h]
__device__ __half g_vt[BATCH * NH * SEQ];   // fp16 transposed [h][s]
__device__ __half g_wt[192 * DM];           // W^T (q|k|v rows), fp16
__device__ float  g_po[BATCH * NSP * SEQ * NH];  // partial O (unnormalized)
__device__ float  g_pm[BATCH * NSP * SEQ];       // partial row max
__device__ float  g_pl[BATCH * NSP * SEQ];       // partial row sum

// mma.sync m16n8k16 fp16 (sm_80+ PTX; tensor pipe)
__device__ __forceinline__ void mma_f16(float d[4], const uint32_t a[4],
                                        uint32_t b0, uint32_t b1) {
    asm volatile(
        "mma.sync.aligned.m16n8k16.row.col.f32.f16.f16.f32 "
        "{%0,%1,%2,%3}, {%4,%5,%6,%7}, {%8,%9}, {%0,%1,%2,%3};\n"
        : "+f"(d[0]), "+f"(d[1]), "+f"(d[2]), "+f"(d[3])
        : "r"(a[0]), "r"(a[1]), "r"(a[2]), "r"(a[3]), "r"(b0), "r"(b1));
}

__device__ __forceinline__ void ldmatrix_x4(uint32_t r[4], uint32_t addr) {
    asm volatile(
        "ldmatrix.sync.aligned.m8n8.x4.shared.b16 {%0,%1,%2,%3}, [%4];\n"
        : "=r"(r[0]), "=r"(r[1]), "=r"(r[2]), "=r"(r[3]) : "r"(addr));
}

__device__ __forceinline__ void cp_async16(uint32_t saddr, const void* gptr) {
    asm volatile("cp.async.cg.shared.global [%0], [%1], 16;\n"
                 :: "r"(saddr), "l"(gptr));
}
__device__ __forceinline__ void cp_commit() {
    asm volatile("cp.async.commit_group;\n");
}
__device__ __forceinline__ void cp_wait0() {
    asm volatile("cp.async.wait_group 0;\n");
}
__device__ __forceinline__ void cp_wait1() {
    asm volatile("cp.async.wait_group 1;\n");
}

__device__ __forceinline__ uint32_t smem_u32(const void* p) {
    uint32_t a;
    asm("{ .reg .u64 t; cvta.to.shared.u64 t, %1; cvt.u32.u64 %0, t; }"
        : "=r"(a) : "l"(p));
    return a;
}

__device__ __forceinline__ uint2 c4h(float4 v) {
    __half2 a = __floats2half2_rn(v.x, v.y);
    __half2 b = __floats2half2_rn(v.z, v.w);
    uint2 r;
    r.x = *(uint32_t*)&a;
    r.y = *(uint32_t*)&b;
    return r;
}

// =================================================================
// Kernel 0: transpose W (q|k|v) -> g_wt[192][1024] fp16.
// =================================================================
__global__ __launch_bounds__(256) void wt_kernel(
    const float* __restrict__ Wq,
    const float* __restrict__ Wk,
    const float* __restrict__ Wv)
{
    __shared__ float t[16][65];
    const int tid = threadIdx.x;
    const int k0  = blockIdx.x * 16;
    const int y   = blockIdx.y;
    const float* W = (y == 0) ? Wq : (y == 1) ? Wk : Wv;

    #pragma unroll
    for (int i = 0; i < 4; i++) {
        const int idx = tid + i * 256;
        const int kk = idx >> 6, nn = idx & 63;
        t[kk][nn] = W[(k0 + kk) * NH + nn];
    }
    __syncthreads();
    #pragma unroll
    for (int i = 0; i < 4; i++) {
        const int idx = tid + i * 256;
        const int nn = idx >> 4, kk = idx & 15;
        g_wt[(y * 64 + nn) * DM + k0 + kk] = __float2half(t[kk][nn]);
    }
}

// =================================================================
// Kernel 1: QKV projection, fp16 m16n8k16 (R15 — known good).
// =================================================================
#define KC    64
#define QST   72
#define QA_OFF 0
#define QB_OFF (2 * 64 * QST * 2)
#define QBIAS_OFF (QB_OFF + 2 * 192 * QST * 2)
#define QSMEM (QBIAS_OFF + 192 * 4)

__global__ __launch_bounds__(256) void qkv_mma_kernel(
    const float* __restrict__ x,
    const float* __restrict__ bq,
    const float* __restrict__ bk,
    const float* __restrict__ bv)
{
    extern __shared__ char smem[];
    __half* As = (__half*)(smem + QA_OFF);
    __half* Bs = (__half*)(smem + QB_OFF);
    float* bias_sm = (float*)(smem + QBIAS_OFF);
    const uint32_t sA = smem_u32(As);
    const uint32_t sB = smem_u32(Bs);

    const int tid  = threadIdx.x;
    const int wid  = tid >> 5;
    const int lane = tid & 31;
    const int m0   = blockIdx.x * 64;
    const int wm   = wid >> 2;
    const int wn   = wid & 3;
    const int gid  = lane >> 2;
    const int tig  = lane & 3;

    if (tid < 64)        bias_sm[tid] = bq[tid];
    else if (tid < 128)  bias_sm[tid] = bk[tid - 64];
    else if (tid < 192)  bias_sm[tid] = bv[tid - 128];

    float d[2][6][4];
    #pragma unroll
    for (int i = 0; i < 2; i++)
        #pragma unroll
        for (int j = 0; j < 6; j++)
            #pragma unroll
            for (int c = 0; c < 4; c++) d[i][j][c] = 0.f;

    float4 rx[4];

    auto ldg_x = [&](int c) {
        const int kc = c * KC;
        #pragma unroll
        for (int i = 0; i < 4; i++) {
            const int idx = tid + 256 * i;
            rx[i] = *(const float4*)&x[(size_t)(m0 + (idx >> 4)) * DM + kc + (idx & 15) * 4];
        }
    };
    auto commit_x = [&](int buf) {
        #pragma unroll
        for (int i = 0; i < 4; i++) {
            const int idx = tid + 256 * i;
            *(uint2*)&As[(buf * 64 + (idx >> 4)) * QST + (idx & 15) * 4] = c4h(rx[i]);
        }
    };
    auto casync_w = [&](int c, int buf) {
        const int kc = c * KC;
        #pragma unroll
        for (int i = 0; i < 6; i++) {
            const int idx = tid + 256 * i;
            const int row = idx >> 3, seg = idx & 7;
            cp_async16(sB + ((buf * 192 + row) * QST + seg * 8) * 2,
                       &g_wt[(size_t)row * DM + kc + seg * 8]);
        }
        cp_commit();
    };

    const int NC = DM / KC;

    casync_w(0, 0);
    ldg_x(0);
    casync_w(1, 1);
    commit_x(0);
    ldg_x(1);
    cp_wait1();
    __syncthreads();

    for (int it = 0; it < NC; it++) {
        const int buf  = it & 1;
        const int nbuf = buf ^ 1;

        #pragma unroll
        for (int ks = 0; ks < 4; ks++) {
            const int k0 = ks * 16;
            uint32_t a[2][4];
            #pragma unroll
            for (int mt = 0; mt < 2; mt++) {
                const int m = wm * 32 + mt * 16 + (lane & 15);
                const int c = k0 + (lane >> 4) * 8;
                ldmatrix_x4(a[mt], sA + ((buf * 64 + m) * QST + c) * 2);
            }
            uint32_t bfr[3][4];
            #pragma unroll
            for (int p = 0; p < 3; p++) {
                const int n = wn * 48 + 16 * p + ((lane >> 4) << 3) + (lane & 7);
                const int c = k0 + ((lane >> 3) & 1) * 8;
                ldmatrix_x4(bfr[p], sB + ((buf * 192 + n) * QST + c) * 2);
            }
            #pragma unroll
            for (int nt = 0; nt < 6; nt++) {
                const int p = nt >> 1;
                const uint32_t b0 = bfr[p][(nt & 1) * 2];
                const uint32_t b1 = bfr[p][(nt & 1) * 2 + 1];
                mma_f16(d[0][nt], a[0], b0, b1);
                mma_f16(d[1][nt], a[1], b0, b1);
            }
        }

        if (it + 1 < NC) commit_x(nbuf);
        if (it + 2 < NC) ldg_x(it + 2);
        if (it + 1 < NC) cp_wait0();
        __syncthreads();
        if (it + 2 < NC) casync_w(it + 2, buf);
    }

    #pragma unroll
    for (int mt = 0; mt < 2; mt++) {
        const int row = m0 + wm * 32 + mt * 16 + gid;
        #pragma unroll
        for (int nt = 0; nt < 6; nt++) {
            const int col0 = wn * 48 + nt * 8;
            __half* dst = (col0 < 64) ? g_q : (col0 < 128) ? g_k : g_v;
            const float scale = (col0 < 64) ? 0.125f : 1.0f;
            const int h0 = (col0 & 63) + 2 * tig;
            const float b0 = bias_sm[col0 + 2 * tig];
            const float b1 = bias_sm[col0 + 2 * tig + 1];
            __half2 w0 = __floats2half2_rn((d[mt][nt][0] + b0) * scale,
                                           (d[mt][nt][1] + b1) * scale);
            __half2 w1 = __floats2half2_rn((d[mt][nt][2] + b0) * scale,
                                           (d[mt][nt][3] + b1) * scale);
            *(uint32_t*)&dst[(size_t)row * NH + h0]       = *(uint32_t*)&w0;
            *(uint32_t*)&dst[(size_t)(row + 8) * NH + h0] = *(uint32_t*)&w1;
        }
    }
}

// =================================================================
// Kernel 1b: transpose V -> g_vt [b][h][s] fp16.
// =================================================================
__global__ __launch_bounds__(256) void vt_kernel()
{
    __shared__ __half t[64][72];
    const int tid = threadIdx.x;
    const int s0  = blockIdx.x * 64;
    const int b   = blockIdx.y;
    const __half* src = g_v + (size_t)b * SEQ * NH;
    __half* dst = g_vt + (size_t)b * NH * SEQ;

    #pragma unroll
    for (int i = 0; i < 2; i++) {
        const int idx = tid + 256 * i;
        const int row = idx >> 3, seg = (idx & 7) * 8;
        *(uint4*)&t[row][seg] = *(const uint4*)&src[(size_t)(s0 + row) * NH + seg];
    }
    __syncthreads();
    #pragma unroll
    for (int i = 0; i < 2; i++) {
        const int idx = tid + 256 * i;
        const int h = idx >> 3, seg = (idx & 7) * 8;
        uint32_t w[4];
        #pragma unroll
        for (int j = 0; j < 4; j++) {
            __half2 hh = __halves2half2(t[seg + 2 * j][h], t[seg + 2 * j + 1][h]);
            w[j] = *(uint32_t*)&hh;
        }
        uint4 o = make_uint4(w[0], w[1], w[2], w[3]);
        *(uint4*)&dst[(size_t)h * SEQ + s0 + seg] = o;
    }
}

// =================================================================
// Kernel 2: split-K causal flash attention, fp16 m16n8k16.
// NEW: ldmatrix.x4 B-fragments (S and PV) + cp.async KV tile copies.
// =================================================================
#define AST 72

__global__ __launch_bounds__(64) void attn_split_kernel()
{
    __shared__ __half ks[2][64][AST];
    __shared__ __half vs[2][64][AST];

    const int tid = threadIdx.x;
    const int qt  = 63 - blockIdx.x;      // heavy blocks first
    const int sp  = blockIdx.y;
    const int b   = blockIdx.z;
    const int q0  = qt * 32;
    const int nk  = (qt >> 1) + 1;
    const int ts  = (nk + NSP - 1) / NSP;
    const int tb  = sp * ts;
    const int te  = (tb + ts < nk) ? (tb + ts) : nk;

    float* PO = g_po + ((size_t)(b * NSP + sp) * SEQ + q0) * NH;
    float* PM = g_pm + (size_t)(b * NSP + sp) * SEQ + q0;
    float* PL = g_pl + (size_t)(b * NSP + sp) * SEQ + q0;

    if (tb >= nk) {
        #pragma unroll
        for (int i = 0; i < 4; i++) {
            const int idx = tid + 64 * i;
            const int row = idx >> 3, cg = (idx & 7) * 8;
            float4 z = make_float4(0.f, 0.f, 0.f, 0.f);
            *(float4*)&PO[(size_t)row * NH + cg]     = z;
            *(float4*)&PO[(size_t)row * NH + cg + 4] = z;
        }
        if (tid < 32) { PM[tid] = -1e30f; PL[tid] = 0.f; }
        return;
    }

    const __half* Q  = g_q  + (size_t)b * SEQ * NH;
    const __half* K  = g_k  + (size_t)b * SEQ * NH;
    const __half* VT = g_vt + (size_t)b * NH * SEQ;

    const uint32_t sk = smem_u32(ks);
    const uint32_t sv = smem_u32(vs);

    const int wid  = tid >> 5;
    const int lane = tid & 31;
    const int gid  = lane >> 2;
    const int tig  = lane & 3;
    const int r0   = wid * 16 + gid;
    const int r1   = r0 + 8;

    // ldmatrix B-frag addressing (same mapping as qkv — proven)
    const int ldm_n = ((lane >> 4) << 3) + (lane & 7);   // row within 16-group
    const int ldm_c = ((lane >> 3) & 1) * 8;             // k-offset 0/8

    // async KV tile copy
    auto copy_tile = [&](int t) {
        const int kb = t * 64;
        const int bn = t & 1;
        #pragma unroll
        for (int i = 0; i < 8; i++) {
            const int idx = tid + 64 * i;
            const int row = idx >> 3, seg = (idx & 7) * 8;
            cp_async16(sk + ((bn * 64 + row) * AST + seg) * 2,
                       &K[(size_t)(kb + row) * NH + seg]);
            cp_async16(sv + ((bn * 64 + row) * AST + seg) * 2,
                       &VT[(size_t)row * SEQ + kb + seg]);
        }
        cp_commit();
    };

    uint32_t qa[4][4];
    #pragma unroll
    for (int kc = 0; kc < 4; kc++) {
        const __half* p0 = &Q[(size_t)(q0 + r0) * NH + kc * 16 + 2 * tig];
        const __half* p1 = &Q[(size_t)(q0 + r1) * NH + kc * 16 + 2 * tig];
        qa[kc][0] = *(const uint32_t*)p0;
        qa[kc][1] = *(const uint32_t*)p1;
        qa[kc][2] = *(const uint32_t*)(p0 + 8);
        qa[kc][3] = *(const uint32_t*)(p1 + 8);
    }

    copy_tile(tb);

    float m0 = -1e30f, m1 = -1e30f, l0 = 0.f, l1 = 0.f;
    float d_o[8][4];
    #pragma unroll
    for (int nt = 0; nt < 8; nt++)
        #pragma unroll
        for (int c = 0; c < 4; c++) d_o[nt][c] = 0.f;

    for (int t = tb; t < te; t++) {
        // issue copy of t+1 (targets buffer last read in tile t-1, retired
        // by the end-of-tile barrier), then wait for tile t's data.
        if (t + 1 < te) { copy_tile(t + 1); cp_wait1(); }
        else            { cp_wait0(); }
        __syncthreads();

        const int bn = t & 1;

        // ---- S = Q K^T (ldmatrix B-frags) ----
        float sd[8][4];
        #pragma unroll
        for (int nt = 0; nt < 8; nt++)
            #pragma unroll
            for (int c = 0; c < 4; c++) sd[nt][c] = 0.f;

        #pragma unroll
        for (int kc = 0; kc < 4; kc++) {
            uint32_t bfr[4][4];
            #pragma unroll
            for (int g = 0; g < 4; g++) {
                const int n = 16 * g + ldm_n;
                const int c = kc * 16 + ldm_c;
                ldmatrix_x4(bfr[g], sk + ((bn * 64 + n) * AST + c) * 2);
            }
            #pragma unroll
            for (int nt = 0; nt < 8; nt++) {
                const uint32_t b0 = bfr[nt >> 1][(nt & 1) * 2];
                const uint32_t b1 = bfr[nt >> 1][(nt & 1) * 2 + 1];
                mma_f16(sd[nt], qa[kc], b0, b1);
            }
        }

        // ---- causal mask (diagonal tile only) ----
        if (t == nk - 1) {
            #pragma unroll
            for (int nt = 0; nt < 8; nt++) {
                const int kg = t * 64 + 8 * nt + 2 * tig;
                if (kg     > q0 + r0) sd[nt][0] = -1e30f;
                if (kg + 1 > q0 + r0) sd[nt][1] = -1e30f;
                if (kg     > q0 + r1) sd[nt][2] = -1e30f;
                if (kg + 1 > q0 + r1) sd[nt][3] = -1e30f;
            }
        }

        // ---- warp-local online softmax ----
        float t0 = -1e30f, t1 = -1e30f;
        #pragma unroll
        for (int nt = 0; nt < 8; nt++) {
            t0 = fmaxf(t0, fmaxf(sd[nt][0], sd[nt][1]));
            t1 = fmaxf(t1, fmaxf(sd[nt][2], sd[nt][3]));
        }
        t0 = fmaxf(t0, __shfl_xor_sync(0xffffffffu, t0, 1));
        t0 = fmaxf(t0, __shfl_xor_sync(0xffffffffu, t0, 2));
        t1 = fmaxf(t1, __shfl_xor_sync(0xffffffffu, t1, 1));
        t1 = fmaxf(t1, __shfl_xor_sync(0xffffffffu, t1, 2));
        const float mn0 = fmaxf(m0, t0);
        const float mn1 = fmaxf(m1, t1);
        const float f0 = __expf(m0 - mn0);
        const float f1 = __expf(m1 - mn1);
        m0 = mn0; m1 = mn1;
        #pragma unroll
        for (int nt = 0; nt < 8; nt++) {
            d_o[nt][0] *= f0; d_o[nt][1] *= f0;
            d_o[nt][2] *= f1; d_o[nt][3] *= f1;
        }

        uint32_t pa[4][4];
        float s0 = 0.f, s1 = 0.f;
        #pragma unroll
        for (int nt = 0; nt < 8; nt++) {
            __half2 h0 = __floats2half2_rn(__expf(sd[nt][0] - mn0),
                                           __expf(sd[nt][1] - mn0));
            __half2 h1 = __floats2half2_rn(__expf(sd[nt][2] - mn1),
                                           __expf(sd[nt][3] - mn1));
            float2 g0 = __half22float2(h0);
            float2 g1 = __half22float2(h1);
            s0 += g0.x + g0.y;
            s1 += g1.x + g1.y;
            const int kc = nt >> 1;
            if ((nt & 1) == 0) {
                pa[kc][0] = *(uint32_t*)&h0;
                pa[kc][1] = *(uint32_t*)&h1;
            } else {
                pa[kc][2] = *(uint32_t*)&h0;
                pa[kc][3] = *(uint32_t*)&h1;
            }
        }
        s0 += __shfl_xor_sync(0xffffffffu, s0, 1);
        s0 += __shfl_xor_sync(0xffffffffu, s0, 2);
        s1 += __shfl_xor_sync(0xffffffffu, s1, 1);
        s1 += __shfl_xor_sync(0xffffffffu, s1, 2);
        l0 = l0 * f0 + s0;
        l1 = l1 * f1 + s1;

        // ---- O += P V (ldmatrix B-frags from V^T) ----
        #pragma unroll
        for (int kc = 0; kc < 4; kc++) {
            uint32_t bfr[4][4];
            #pragma unroll
            for (int g = 0; g < 4; g++) {
                const int n = 16 * g + ldm_n;
                const int c = kc * 16 + ldm_c;
                ldmatrix_x4(bfr[g], sv + ((bn * 64 + n) * AST + c) * 2);
            }
            #pragma unroll
            for (int nt = 0; nt < 8; nt++) {
                const uint32_t b0 = bfr[nt >> 1][(nt & 1) * 2];
                const uint32_t b1 = bfr[nt >> 1][(nt & 1) * 2 + 1];
                mma_f16(d_o[nt], pa[kc], b0, b1);
            }
        }
        __syncthreads();
    }

    if (tig == 0) {
        PM[r0] = m0; PL[r0] = l0;
        PM[r1] = m1; PL[r1] = l1;
    }
    #pragma unroll
    for (int nt = 0; nt < 8; nt++) {
        const int cc = 8 * nt + 2 * tig;
        *(float2*)&PO[(size_t)r0 * NH + cc] = make_float2(d_o[nt][0], d_o[nt][1]);
        *(float2*)&PO[(size_t)r1 * NH + cc] = make_float2(d_o[nt][2], d_o[nt][3]);
    }
}

// =================================================================
// Kernel 3: combine partials -> out.
// =================================================================
__global__ __launch_bounds__(256) void comb_kernel(float* __restrict__ out)
{
    const int tid = threadIdx.x;
    const int s   = blockIdx.x * 16 + (tid >> 4);
    const int b   = blockIdx.y;
    const int cg  = (tid & 15) * 4;

    float m[NSP], l[NSP];
    float4 o[NSP];
    #pragma unroll
    for (int i = 0; i < NSP; i++) {
        m[i] = g_pm[(size_t)(b * NSP + i) * SEQ + s];
        l[i] = g_pl[(size_t)(b * NSP + i) * SEQ + s];
        o[i] = *(const float4*)&g_po[((size_t)(b * NSP + i) * SEQ + s) * NH + cg];
    }
    float M = m[0];
    #pragma unroll
    for (int i = 1; i < NSP; i++) M = fmaxf(M, m[i]);
    float w[NSP], L = 0.f;
    #pragma unroll
    for (int i = 0; i < NSP; i++) {
        w[i] = __expf(m[i] - M);
        L += w[i] * l[i];
    }
    const float inv = 1.f / L;

    float4 acc = make_float4(0.f, 0.f, 0.f, 0.f);
    #pragma unroll
    for (int i = 0; i < NSP; i++) {
        acc.x += w[i] * o[i].x;
        acc.y += w[i] * o[i].y;
        acc.z += w[i] * o[i].z;
        acc.w += w[i] * o[i].w;
    }
    *(float4*)&out[(size_t)(b * SEQ + s) * NH + cg] =
        make_float4(acc.x * inv, acc.y * inv, acc.z * inv, acc.w * inv);
}

// =================================================================
// launch
// =================================================================
extern "C" void kernel_launch(void* const* d_in, const int* in_sizes, int n_in,
                              void* d_out, int out_size)
{
    (void)in_sizes; (void)n_in; (void)out_size;
    const float* x  = (const float*)d_in[0];
    const float* Wq = (const float*)d_in[1];
    const float* bq = (const float*)d_in[2];
    const float* Wk = (const float*)d_in[3];
    const float* bk = (const float*)d_in[4];
    const float* Wv = (const float*)d_in[5];
    const float* bv = (const float*)d_in[6];
    float* out = (float*)d_out;

    cudaFuncSetAttribute(qkv_mma_kernel,
                         cudaFuncAttributeMaxDynamicSharedMemorySize, QSMEM);

    wt_kernel<<<dim3(64, 3), 256>>>(Wq, Wk, Wv);
    qkv_mma_kernel<<<(BATCH * SEQ) / 64, 256, QSMEM>>>(x, bq, bk, bv);
    vt_kernel<<<dim3(SEQ / 64, BATCH), 256>>>();
    attn_split_kernel<<<dim3(64, NSP, BATCH), 64>>>();
    comb_kernel<<<dim3(SEQ / 16, BATCH), 256>>>(out);
}